// round 1
// baseline (speedup 1.0000x reference)
#include <cuda_runtime.h>
#include <math.h>

#define N_NODES 50000
#define N_FEAT 512
#define HIDDEN 128
#define N_CLASSES 40

// ---------------- scratch (device globals: no allocation allowed) ----------
__device__ float g_dinv[N_NODES];
__device__ float g_h[N_NODES * HIDDEN];        // GEMM1 out, later reused for relu(h1)
__device__ float g_agg1[N_NODES * HIDDEN];     // layer-1 aggregation
__device__ float g_lp[N_NODES * N_CLASSES];    // h1 @ W2
__device__ float g_agg2[N_NODES * N_CLASSES];  // layer-2 aggregation
__device__ int   g_is64;                       // edge_index dtype flag

// ---------------- edge index access (int32 / int64 hedge) ------------------
__global__ void k_detect_dtype(const int* e32) {
    // If edges are int64 (values < 2^31, >=0), every high 32-bit word is 0.
    // If int32, odd int32 slots are random values in [0, 50000): P(all 0) ~ 0.
    bool is64 = true;
    for (int i = 1; i < 64; i += 2) {
        if (e32[i] != 0) { is64 = false; break; }
    }
    g_is64 = is64 ? 1 : 0;
}

__device__ __forceinline__ int edge_at(const void* ei, int idx, int is64) {
    if (is64) return (int)((const long long*)ei)[idx];
    return ((const int*)ei)[idx];
}

// ---------------- degree / normalization -----------------------------------
__global__ void k_init_deg() {
    int i = blockIdx.x * blockDim.x + threadIdx.x;
    if (i < N_NODES) g_dinv[i] = 1.0f;   // self loop
}

__global__ void k_deg_accum(const void* __restrict__ ei, int E) {
    int i = blockIdx.x * blockDim.x + threadIdx.x;
    if (i >= E) return;
    int is64 = g_is64;
    int d = edge_at(ei, E + i, is64);
    atomicAdd(&g_dinv[d], 1.0f);
}

__global__ void k_finish_dinv() {
    int i = blockIdx.x * blockDim.x + threadIdx.x;
    if (i < N_NODES) g_dinv[i] = rsqrtf(g_dinv[i]);
}

// ---------------- GEMM1: g_h = x @ W1   (M x 512) @ (512 x 128) ------------
__global__ __launch_bounds__(256) void k_sgemm1(const float* __restrict__ A,
                                                const float* __restrict__ B) {
    const int K = N_FEAT, N = HIDDEN, M = N_NODES;
    __shared__ float As[16][132];  // transposed A tile [k][m], padded
    __shared__ float Bs[16][132];  // B tile [k][n], padded

    int tid = threadIdx.x;
    int blockM = blockIdx.x * 128;
    int tr = tid >> 4;       // 0..15
    int tc = tid & 15;       // 0..15

    float acc[8][8];
#pragma unroll
    for (int i = 0; i < 8; i++)
#pragma unroll
        for (int j = 0; j < 8; j++) acc[i][j] = 0.0f;

    for (int kt = 0; kt < K; kt += 16) {
        // A tile: 128 rows x 16 cols = 512 float4
#pragma unroll
        for (int it = 0; it < 2; it++) {
            int e = tid + it * 256;
            int ar = e >> 2;          // 0..127
            int ac4 = e & 3;          // 0..3
            int grow = blockM + ar;
            float4 v = make_float4(0.f, 0.f, 0.f, 0.f);
            if (grow < M) v = *(const float4*)&A[(size_t)grow * K + kt + ac4 * 4];
            As[ac4 * 4 + 0][ar] = v.x;
            As[ac4 * 4 + 1][ar] = v.y;
            As[ac4 * 4 + 2][ar] = v.z;
            As[ac4 * 4 + 3][ar] = v.w;
        }
        // B tile: 16 rows x 128 cols = 512 float4
#pragma unroll
        for (int it = 0; it < 2; it++) {
            int e = tid + it * 256;
            int br = e >> 5;          // 0..15
            int bc4 = e & 31;         // 0..31
            float4 v = *(const float4*)&B[(size_t)(kt + br) * N + bc4 * 4];
            *(float4*)&Bs[br][bc4 * 4] = v;
        }
        __syncthreads();

#pragma unroll
        for (int k = 0; k < 16; k++) {
            float ra[8], rb[8];
#pragma unroll
            for (int i = 0; i < 8; i++) ra[i] = As[k][tr * 8 + i];
#pragma unroll
            for (int j = 0; j < 8; j++) rb[j] = Bs[k][tc * 8 + j];
#pragma unroll
            for (int i = 0; i < 8; i++)
#pragma unroll
                for (int j = 0; j < 8; j++) acc[i][j] += ra[i] * rb[j];
        }
        __syncthreads();
    }

#pragma unroll
    for (int i = 0; i < 8; i++) {
        int row = blockM + tr * 8 + i;
        if (row < M) {
#pragma unroll
            for (int j = 0; j < 8; j += 4) {
                *(float4*)&g_h[(size_t)row * N + tc * 8 + j] =
                    make_float4(acc[i][j], acc[i][j + 1], acc[i][j + 2], acc[i][j + 3]);
            }
        }
    }
}

// ---------------- layer-1 aggregation ---------------------------------------
__global__ void k_agg1_init() {
    int t = blockIdx.x * blockDim.x + threadIdx.x;   // N_NODES * 32 float4 slots
    if (t >= N_NODES * 32) return;
    int n = t >> 5;
    int c4 = t & 31;
    float di = g_dinv[n];
    float s = di * di;
    float4 v = *(const float4*)&g_h[(size_t)n * HIDDEN + c4 * 4];
    v.x *= s; v.y *= s; v.z *= s; v.w *= s;
    *(float4*)&g_agg1[(size_t)n * HIDDEN + c4 * 4] = v;
}

__global__ void k_agg1_edges(const void* __restrict__ ei, int E) {
    int gid = blockIdx.x * blockDim.x + threadIdx.x;   // E*32 threads
    int edge = gid >> 5;
    if (edge >= E) return;
    int lane = gid & 31;
    int is64 = g_is64;
    int s = edge_at(ei, edge, is64);
    int d = edge_at(ei, E + edge, is64);
    float norm = g_dinv[s] * g_dinv[d];
    float4 v = *(const float4*)&g_h[(size_t)s * HIDDEN + lane * 4];
    float* o = &g_agg1[(size_t)d * HIDDEN + lane * 4];
    atomicAdd(o + 0, norm * v.x);
    atomicAdd(o + 1, norm * v.y);
    atomicAdd(o + 2, norm * v.z);
    atomicAdd(o + 3, norm * v.w);
}

__global__ void k_relu_bias(const float* __restrict__ b1) {
    int t = blockIdx.x * blockDim.x + threadIdx.x;
    if (t >= N_NODES * HIDDEN) return;
    int c = t & (HIDDEN - 1);
    g_h[t] = fmaxf(g_agg1[t] + b1[c], 0.0f);   // reuse g_h for h1
}

// ---------------- GEMM2: g_lp = h1 @ W2  (M x 128) @ (128 x 40) -------------
__global__ __launch_bounds__(256) void k_gemm2(const float* __restrict__ W2) {
    __shared__ float sW[HIDDEN * N_CLASSES];   // 5120 floats
    __shared__ float sH[32 * HIDDEN];          // 4096 floats
    int tid = threadIdx.x;
    int row0 = blockIdx.x * 32;

    for (int i = tid; i < HIDDEN * N_CLASSES; i += 256) sW[i] = W2[i];
    for (int i = tid; i < 32 * HIDDEN / 4; i += 256) {
        int r = i >> 5;        // 0..31
        int c4 = i & 31;       // 0..31
        int grow = row0 + r;
        float4 v = make_float4(0.f, 0.f, 0.f, 0.f);
        if (grow < N_NODES) v = *(const float4*)&g_h[(size_t)grow * HIDDEN + c4 * 4];
        *(float4*)&sH[r * HIDDEN + c4 * 4] = v;
    }
    __syncthreads();

#pragma unroll
    for (int p = 0; p < 5; p++) {
        int o = tid + p * 256;            // 1280 outputs
        int r = o / N_CLASSES;
        int c = o - r * N_CLASSES;
        float acc = 0.0f;
#pragma unroll 8
        for (int k = 0; k < HIDDEN; k++) acc += sH[r * HIDDEN + k] * sW[k * N_CLASSES + c];
        int grow = row0 + r;
        if (grow < N_NODES) g_lp[(size_t)grow * N_CLASSES + c] = acc;
    }
}

// ---------------- layer-2 aggregation ---------------------------------------
__global__ void k_agg2_init() {
    int t = blockIdx.x * blockDim.x + threadIdx.x;
    if (t >= N_NODES * N_CLASSES) return;
    int n = t / N_CLASSES;
    float di = g_dinv[n];
    g_agg2[t] = di * di * g_lp[t];
}

__global__ void k_agg2_edges(const void* __restrict__ ei, int E) {
    int gid = blockIdx.x * blockDim.x + threadIdx.x;   // E*8 threads
    int edge = gid >> 3;
    if (edge >= E) return;
    int lane = gid & 7;             // 8 lanes x 5 cols
    int is64 = g_is64;
    int s = edge_at(ei, edge, is64);
    int d = edge_at(ei, E + edge, is64);
    float norm = g_dinv[s] * g_dinv[d];
    const float* src = &g_lp[(size_t)s * N_CLASSES + lane * 5];
    float* dst = &g_agg2[(size_t)d * N_CLASSES + lane * 5];
#pragma unroll
    for (int j = 0; j < 5; j++) atomicAdd(dst + j, norm * src[j]);
}

// ---------------- log_softmax + output --------------------------------------
__global__ void k_logsoftmax(const float* __restrict__ b2, float* __restrict__ out,
                             int write_logits) {
    int warp = (blockIdx.x * blockDim.x + threadIdx.x) >> 5;
    int lane = threadIdx.x & 31;
    if (warp >= N_NODES) return;
    const float* row = &g_agg2[(size_t)warp * N_CLASSES];

    float v0 = row[lane] + b2[lane];                       // lane < 32, always valid (40 > 32)
    float v1 = (lane < 8) ? row[32 + lane] + b2[32 + lane] : -INFINITY;

    float m = fmaxf(v0, v1);
#pragma unroll
    for (int off = 16; off > 0; off >>= 1)
        m = fmaxf(m, __shfl_xor_sync(0xFFFFFFFFu, m, off));

    float sum = __expf(v0 - m) + ((lane < 8) ? __expf(v1 - m) : 0.0f);
#pragma unroll
    for (int off = 16; off > 0; off >>= 1)
        sum += __shfl_xor_sync(0xFFFFFFFFu, sum, off);

    float lse = m + logf(sum);

    float* o = &out[(size_t)warp * N_CLASSES];
    o[lane] = v0 - lse;
    if (lane < 8) o[32 + lane] = v1 - lse;
    if (write_logits) {
        float* o2 = &out[(size_t)N_NODES * N_CLASSES + (size_t)warp * N_CLASSES];
        o2[lane] = v0;
        if (lane < 8) o2[32 + lane] = v1;
    }
}

// ---------------- launch -----------------------------------------------------
extern "C" void kernel_launch(void* const* d_in, const int* in_sizes, int n_in,
                              void* d_out, int out_size) {
    const float* x  = (const float*)d_in[0];
    const void*  ei = d_in[1];
    const float* W1 = (const float*)d_in[2];
    const float* b1 = (const float*)d_in[3];
    const float* W2 = (const float*)d_in[4];
    const float* b2 = (const float*)d_in[5];
    float* out = (float*)d_out;

    int E = in_sizes[1] / 2;
    int write_logits = (out_size >= 2 * N_NODES * N_CLASSES) ? 1 : 0;

    k_detect_dtype<<<1, 1>>>((const int*)ei);

    k_init_deg<<<(N_NODES + 255) / 256, 256>>>();
    k_deg_accum<<<(E + 255) / 256, 256>>>(ei, E);
    k_finish_dinv<<<(N_NODES + 255) / 256, 256>>>();

    k_sgemm1<<<(N_NODES + 127) / 128, 256>>>(x, W1);

    k_agg1_init<<<(N_NODES * 32 + 255) / 256, 256>>>();
    {
        long long threads = (long long)E * 32;
        int blocks = (int)((threads + 255) / 256);
        k_agg1_edges<<<blocks, 256>>>(ei, E);
    }
    k_relu_bias<<<(N_NODES * HIDDEN + 255) / 256, 256>>>(b1);

    k_gemm2<<<(N_NODES + 31) / 32, 256>>>(W2);

    k_agg2_init<<<(N_NODES * N_CLASSES + 255) / 256, 256>>>();
    {
        long long threads = (long long)E * 8;
        int blocks = (int)((threads + 255) / 256);
        k_agg2_edges<<<blocks, 256>>>(ei, E);
    }

    k_logsoftmax<<<(N_NODES + 7) / 8, 256>>>(b2, out, write_logits);
}

// round 4
// speedup vs baseline: 1.8768x; 1.8768x over previous
#include <cuda_runtime.h>
#include <math.h>

#define N_NODES 50000
#define N_FEAT 512
#define HIDDEN 128
#define N_CLASSES 40
#define E_MAX 1600000

// ---------------- scratch (device globals: no allocation allowed) ----------
__device__ float g_dinv[N_NODES];
__device__ int   g_cnt[N_NODES];
__device__ int   g_off[N_NODES + 1];
__device__ int   g_pos[N_NODES];
__device__ int   g_csr_src[E_MAX];
__device__ float g_h[N_NODES * HIDDEN];        // GEMM1 out (x @ W1)
__device__ float g_h1[N_NODES * HIDDEN];       // relu(conv1)
__device__ float g_lp[N_NODES * N_CLASSES];    // h1 @ W2
__device__ int   g_is64;                       // edge_index dtype flag

// ---------------- edge index access (int32 / int64 hedge) ------------------
__device__ __forceinline__ int edge_at(const void* ei, int idx, int is64) {
    if (is64) return (int)((const long long*)ei)[idx];
    return ((const int*)ei)[idx];
}

// zero histogram + detect edge dtype (thread 0)
__global__ void k_zero_cnt(const int* __restrict__ e32) {
    int i = blockIdx.x * blockDim.x + threadIdx.x;
    if (i < N_NODES) g_cnt[i] = 0;
    if (i == 0) {
        // int64 edges in [0, 50000): every odd 32-bit word is 0.
        // int32 edges: odd slots are random node ids; P(64 zeros) ~ 0.
        bool is64 = true;
        for (int k = 1; k < 64; k += 2) {
            if (e32[k] != 0) { is64 = false; break; }
        }
        g_is64 = is64 ? 1 : 0;
    }
}

__global__ void k_hist(const void* __restrict__ ei, int E) {
    int i = blockIdx.x * blockDim.x + threadIdx.x;
    if (i >= E) return;
    int d = edge_at(ei, E + i, g_is64);
    atomicAdd(&g_cnt[d], 1);
}

// single-block chunked exclusive scan; also computes dinv and cursor copy
__global__ __launch_bounds__(1024) void k_scan_dinv() {
    __shared__ int part[1024];
    int tid = threadIdx.x;
    const int CH = (N_NODES + 1023) / 1024;   // 49
    int base = tid * CH;
    int s = 0;
    for (int i = 0; i < CH; i++) {
        int idx = base + i;
        if (idx < N_NODES) s += g_cnt[idx];
    }
    part[tid] = s;
    __syncthreads();
    // Hillis-Steele inclusive scan over 1024 partials (all threads hit all barriers)
    for (int off = 1; off < 1024; off <<= 1) {
        int v = (tid >= off) ? part[tid - off] : 0;
        __syncthreads();
        part[tid] += v;
        __syncthreads();
    }
    int run = (tid == 0) ? 0 : part[tid - 1];
    for (int i = 0; i < CH; i++) {
        int idx = base + i;
        if (idx < N_NODES) {
            int c = g_cnt[idx];
            g_off[idx] = run;
            g_pos[idx] = run;
            g_dinv[idx] = rsqrtf((float)(c + 1));   // + self loop
            run += c;
        }
    }
    if (tid == 1023) g_off[N_NODES] = run;
}

__global__ void k_scatter(const void* __restrict__ ei, int E) {
    int i = blockIdx.x * blockDim.x + threadIdx.x;
    if (i >= E) return;
    int is64 = g_is64;
    int s = edge_at(ei, i, is64);
    int d = edge_at(ei, E + i, is64);
    int p = atomicAdd(&g_pos[d], 1);
    g_csr_src[p] = s;
}

// ---------------- GEMM1: g_h = x @ W1   (M x 512) @ (512 x 128) ------------
__global__ __launch_bounds__(256) void k_sgemm1(const float* __restrict__ A,
                                                const float* __restrict__ B) {
    const int K = N_FEAT, N = HIDDEN, M = N_NODES;
    __shared__ float As[16][132];
    __shared__ float Bs[16][132];

    int tid = threadIdx.x;
    int blockM = blockIdx.x * 128;
    int tr = tid >> 4;
    int tc = tid & 15;

    float acc[8][8];
#pragma unroll
    for (int i = 0; i < 8; i++)
#pragma unroll
        for (int j = 0; j < 8; j++) acc[i][j] = 0.0f;

    for (int kt = 0; kt < K; kt += 16) {
#pragma unroll
        for (int it = 0; it < 2; it++) {
            int e = tid + it * 256;
            int ar = e >> 2;
            int ac4 = e & 3;
            int grow = blockM + ar;
            float4 v = make_float4(0.f, 0.f, 0.f, 0.f);
            if (grow < M) v = *(const float4*)&A[(size_t)grow * K + kt + ac4 * 4];
            As[ac4 * 4 + 0][ar] = v.x;
            As[ac4 * 4 + 1][ar] = v.y;
            As[ac4 * 4 + 2][ar] = v.z;
            As[ac4 * 4 + 3][ar] = v.w;
        }
#pragma unroll
        for (int it = 0; it < 2; it++) {
            int e = tid + it * 256;
            int br = e >> 5;
            int bc4 = e & 31;
            float4 v = *(const float4*)&B[(size_t)(kt + br) * N + bc4 * 4];
            *(float4*)&Bs[br][bc4 * 4] = v;
        }
        __syncthreads();

#pragma unroll
        for (int k = 0; k < 16; k++) {
            float ra[8], rb[8];
#pragma unroll
            for (int i = 0; i < 8; i++) ra[i] = As[k][tr * 8 + i];
#pragma unroll
            for (int j = 0; j < 8; j++) rb[j] = Bs[k][tc * 8 + j];
#pragma unroll
            for (int i = 0; i < 8; i++)
#pragma unroll
                for (int j = 0; j < 8; j++) acc[i][j] += ra[i] * rb[j];
        }
        __syncthreads();
    }

#pragma unroll
    for (int i = 0; i < 8; i++) {
        int row = blockM + tr * 8 + i;
        if (row < M) {
#pragma unroll
            for (int j = 0; j < 8; j += 4) {
                *(float4*)&g_h[(size_t)row * N + tc * 8 + j] =
                    make_float4(acc[i][j], acc[i][j + 1], acc[i][j + 2], acc[i][j + 3]);
            }
        }
    }
}

// ---------------- layer-1 aggregation (CSR gather, fused bias+relu) ---------
__global__ __launch_bounds__(256) void k_agg1(const float* __restrict__ b1) {
    int warp = (blockIdx.x * blockDim.x + threadIdx.x) >> 5;
    if (warp >= N_NODES) return;
    int lane = threadIdx.x & 31;

    const float4* hp = (const float4*)g_h;
    float di = g_dinv[warp];
    int beg = g_off[warp];
    int end = g_off[warp + 1];

    // self loop: dinv^2 * h[d]; factor one dinv outside the loop
    float4 v = __ldg(&hp[(size_t)warp * 32 + lane]);
    float ax = di * v.x, ay = di * v.y, az = di * v.z, aw = di * v.w;

    int e = beg;
    for (; e + 4 <= end; e += 4) {
        int s0 = __ldg(&g_csr_src[e + 0]);
        int s1 = __ldg(&g_csr_src[e + 1]);
        int s2 = __ldg(&g_csr_src[e + 2]);
        int s3 = __ldg(&g_csr_src[e + 3]);
        float w0 = __ldg(&g_dinv[s0]), w1 = __ldg(&g_dinv[s1]);
        float w2 = __ldg(&g_dinv[s2]), w3 = __ldg(&g_dinv[s3]);
        float4 v0 = __ldg(&hp[(size_t)s0 * 32 + lane]);
        float4 v1 = __ldg(&hp[(size_t)s1 * 32 + lane]);
        float4 v2 = __ldg(&hp[(size_t)s2 * 32 + lane]);
        float4 v3 = __ldg(&hp[(size_t)s3 * 32 + lane]);
        ax += w0 * v0.x + w1 * v1.x + w2 * v2.x + w3 * v3.x;
        ay += w0 * v0.y + w1 * v1.y + w2 * v2.y + w3 * v3.y;
        az += w0 * v0.z + w1 * v1.z + w2 * v2.z + w3 * v3.z;
        aw += w0 * v0.w + w1 * v1.w + w2 * v2.w + w3 * v3.w;
    }
    for (; e < end; e++) {
        int s = __ldg(&g_csr_src[e]);
        float w = __ldg(&g_dinv[s]);
        float4 vv = __ldg(&hp[(size_t)s * 32 + lane]);
        ax += w * vv.x; ay += w * vv.y; az += w * vv.z; aw += w * vv.w;
    }

    float4 bb = *(const float4*)&b1[lane * 4];
    float4 o;
    o.x = fmaxf(di * ax + bb.x, 0.0f);
    o.y = fmaxf(di * ay + bb.y, 0.0f);
    o.z = fmaxf(di * az + bb.z, 0.0f);
    o.w = fmaxf(di * aw + bb.w, 0.0f);
    *(float4*)&g_h1[(size_t)warp * HIDDEN + lane * 4] = o;
}

// ---------------- GEMM2: g_lp = h1 @ W2  (M x 128) @ (128 x 40) -------------
__global__ __launch_bounds__(256) void k_gemm2(const float* __restrict__ W2) {
    __shared__ float sW[HIDDEN * N_CLASSES];
    __shared__ float sH[32 * HIDDEN];
    int tid = threadIdx.x;
    int row0 = blockIdx.x * 32;

    for (int i = tid; i < HIDDEN * N_CLASSES; i += 256) sW[i] = W2[i];
    for (int i = tid; i < 32 * HIDDEN / 4; i += 256) {
        int r = i >> 5;
        int c4 = i & 31;
        int grow = row0 + r;
        float4 v = make_float4(0.f, 0.f, 0.f, 0.f);
        if (grow < N_NODES) v = *(const float4*)&g_h1[(size_t)grow * HIDDEN + c4 * 4];
        *(float4*)&sH[r * HIDDEN + c4 * 4] = v;
    }
    __syncthreads();

#pragma unroll
    for (int p = 0; p < 5; p++) {
        int o = tid + p * 256;
        int r = o / N_CLASSES;
        int c = o - r * N_CLASSES;
        float acc = 0.0f;
#pragma unroll 8
        for (int k = 0; k < HIDDEN; k++) acc += sH[r * HIDDEN + k] * sW[k * N_CLASSES + c];
        int grow = row0 + r;
        if (grow < N_NODES) g_lp[(size_t)grow * N_CLASSES + c] = acc;
    }
}

// ---------------- layer-2 aggregation + bias + log_softmax ------------------
__global__ __launch_bounds__(256) void k_agg2(const float* __restrict__ b2,
                                              float* __restrict__ out,
                                              int write_logits) {
    int warp = (blockIdx.x * blockDim.x + threadIdx.x) >> 5;
    if (warp >= N_NODES) return;
    int lane = threadIdx.x & 31;
    bool hi = (lane < 8);

    const float* lp = g_lp;
    float di = g_dinv[warp];
    int beg = g_off[warp];
    int end = g_off[warp + 1];

    float a0 = di * __ldg(&lp[(size_t)warp * N_CLASSES + lane]);
    float a1 = hi ? di * __ldg(&lp[(size_t)warp * N_CLASSES + 32 + lane]) : 0.0f;

    int e = beg;
    for (; e + 4 <= end; e += 4) {
        int s0 = __ldg(&g_csr_src[e + 0]);
        int s1 = __ldg(&g_csr_src[e + 1]);
        int s2 = __ldg(&g_csr_src[e + 2]);
        int s3 = __ldg(&g_csr_src[e + 3]);
        float w0 = __ldg(&g_dinv[s0]), w1 = __ldg(&g_dinv[s1]);
        float w2 = __ldg(&g_dinv[s2]), w3 = __ldg(&g_dinv[s3]);
        a0 += w0 * __ldg(&lp[(size_t)s0 * N_CLASSES + lane])
            + w1 * __ldg(&lp[(size_t)s1 * N_CLASSES + lane])
            + w2 * __ldg(&lp[(size_t)s2 * N_CLASSES + lane])
            + w3 * __ldg(&lp[(size_t)s3 * N_CLASSES + lane]);
        if (hi) {
            a1 += w0 * __ldg(&lp[(size_t)s0 * N_CLASSES + 32 + lane])
                + w1 * __ldg(&lp[(size_t)s1 * N_CLASSES + 32 + lane])
                + w2 * __ldg(&lp[(size_t)s2 * N_CLASSES + 32 + lane])
                + w3 * __ldg(&lp[(size_t)s3 * N_CLASSES + 32 + lane]);
        }
    }
    for (; e < end; e++) {
        int s = __ldg(&g_csr_src[e]);
        float w = __ldg(&g_dinv[s]);
        a0 += w * __ldg(&lp[(size_t)s * N_CLASSES + lane]);
        if (hi) a1 += w * __ldg(&lp[(size_t)s * N_CLASSES + 32 + lane]);
    }

    float v0 = di * a0 + b2[lane];
    float v1 = hi ? di * a1 + b2[32 + lane] : -INFINITY;

    float m = fmaxf(v0, v1);
#pragma unroll
    for (int off = 16; off > 0; off >>= 1)
        m = fmaxf(m, __shfl_xor_sync(0xFFFFFFFFu, m, off));

    float sum = __expf(v0 - m) + (hi ? __expf(v1 - m) : 0.0f);
#pragma unroll
    for (int off = 16; off > 0; off >>= 1)
        sum += __shfl_xor_sync(0xFFFFFFFFu, sum, off);

    float lse = m + logf(sum);

    float* o = &out[(size_t)warp * N_CLASSES];
    o[lane] = v0 - lse;
    if (hi) o[32 + lane] = v1 - lse;
    if (write_logits) {
        float* o2 = &out[(size_t)N_NODES * N_CLASSES + (size_t)warp * N_CLASSES];
        o2[lane] = v0;
        if (hi) o2[32 + lane] = v1;
    }
}

// ---------------- launch -----------------------------------------------------
extern "C" void kernel_launch(void* const* d_in, const int* in_sizes, int n_in,
                              void* d_out, int out_size) {
    const float* x  = (const float*)d_in[0];
    const void*  ei = d_in[1];
    const float* W1 = (const float*)d_in[2];
    const float* b1 = (const float*)d_in[3];
    const float* W2 = (const float*)d_in[4];
    const float* b2 = (const float*)d_in[5];
    float* out = (float*)d_out;

    int E = in_sizes[1] / 2;
    if (E > E_MAX) E = E_MAX;
    int write_logits = (out_size >= 2 * N_NODES * N_CLASSES) ? 1 : 0;

    k_zero_cnt<<<(N_NODES + 255) / 256, 256>>>((const int*)ei);    // launch 1
    k_hist<<<(E + 255) / 256, 256>>>(ei, E);                       // launch 2
    k_scan_dinv<<<1, 1024>>>();                                    // launch 3
    k_scatter<<<(E + 255) / 256, 256>>>(ei, E);                    // launch 4

    k_sgemm1<<<(N_NODES + 127) / 128, 256>>>(x, W1);               // launch 5 (ncu target)

    k_agg1<<<(N_NODES * 32 + 255) / 256, 256>>>(b1);               // launch 6
    k_gemm2<<<(N_NODES + 31) / 32, 256>>>(W2);                     // launch 7
    k_agg2<<<(N_NODES * 32 + 255) / 256, 256>>>(b2, out, write_logits); // launch 8
}